// round 2
// baseline (speedup 1.0000x reference)
#include <cuda_runtime.h>
#include <cstdint>

#define DIM     256
#define NEMBED  512
#define NROWS   131072            // B*T = 32*4096
#define OUT_ELEMS 33554432        // NROWS*DIM
#define LOSS_OFF  33554432
#define IND_OFF   33554433

#define BM 128
#define BN 128
#define BK 128
#define XS_LD 260                 // 256 + 4 (16B-aligned rows, broadcast reads)
#define CS_LD 130                 // 128 + 2 (bank stride 2 -> conflict-free LDS.64)

// floats: xs 128*260=33280, cs 128*130=16640, ssq 512, rssq 128, best 128, red 8
#define SMEM_FLOATS (BM*XS_LD + BN*CS_LD + NEMBED + BM + BM + 8)
#define SMEM_BYTES  (SMEM_FLOATS * 4)

__device__ float g_embed_n[NEMBED * DIM];   // normalized codebook
__device__ float g_ssq[NEMBED];             // per-row sum of squares of normalized row
__device__ float g_sum[DIM];                // sum over rows of normalized codebook
__device__ float g_ssqsum;
__device__ float g_diff;

__device__ __forceinline__ void fma2(unsigned long long& d,
                                     unsigned long long a,
                                     unsigned long long b) {
    asm("fma.rn.f32x2 %0, %1, %2, %0;" : "+l"(d) : "l"(a), "l"(b));
}

// ---------------------------------------------------------------- init ----
__global__ void init_kernel() {
    int t = threadIdx.x;
    g_sum[t] = 0.0f;
    if (t == 0) { g_ssqsum = 0.0f; g_diff = 0.0f; }
}

// ---------------------------------------------- normalize codebook rows ----
__global__ void normalize_kernel(const float* __restrict__ emb) {
    __shared__ float w[8];
    int r = blockIdx.x, t = threadIdx.x;
    float v = emb[r * DIM + t];
    float s = v * v;
    #pragma unroll
    for (int o = 16; o > 0; o >>= 1) s += __shfl_xor_sync(0xffffffffu, s, o);
    if ((t & 31) == 0) w[t >> 5] = s;
    __syncthreads();
    float sum = 0.0f;
    #pragma unroll
    for (int k = 0; k < 8; ++k) sum += w[k];
    float en = __fdiv_rn(v, __fsqrt_rn(sum));   // IEEE: matches jnp q/norm
    g_embed_n[r * DIM + t] = en;
    atomicAdd(&g_sum[t], en);

    float s2 = en * en;
    #pragma unroll
    for (int o = 16; o > 0; o >>= 1) s2 += __shfl_xor_sync(0xffffffffu, s2, o);
    __syncthreads();
    if ((t & 31) == 0) w[t >> 5] = s2;
    __syncthreads();
    if (t == 0) {
        float tot = 0.0f;
        #pragma unroll
        for (int k = 0; k < 8; ++k) tot += w[k];
        g_ssq[r] = tot;
        atomicAdd(&g_ssqsum, tot);
    }
}

// ------------------------------------- main: GEMM+argmax+gather+MSE+out ----
__global__ void __launch_bounds__(256, 1)
main_kernel(const float* __restrict__ input,
            float* __restrict__ out,
            float* __restrict__ ind_out) {
    extern __shared__ float smf[];
    float* xs     = smf;
    float* cs     = xs + BM * XS_LD;
    float* ssq_s  = cs + BN * CS_LD;
    float* rssq_s = ssq_s + NEMBED;
    int*   best_s = (int*)(rssq_s + BM);
    float* red    = (float*)(best_s + BM);

    const int tid = threadIdx.x;
    const int tx  = tid & 15;
    const int ty  = tid >> 4;
    const size_t n0 = (size_t)blockIdx.x * BM;

    // load 128x256 input tile (read once from HBM)
    #pragma unroll
    for (int it = 0; it < 32; ++it) {
        int idx = tid + it * 256;          // 0..8191
        int m = idx >> 6, d4 = idx & 63;
        float4 v = *(const float4*)(input + (n0 + m) * DIM + d4 * 4);
        *(float4*)(xs + m * XS_LD + d4 * 4) = v;
    }
    ssq_s[tid]       = g_ssq[tid];
    ssq_s[tid + 256] = g_ssq[tid + 256];
    __syncthreads();

    // per-row ||x||^2 (fp32) — needed to replicate the reference's dist rounding
    {
        int m = tid >> 1, half = tid & 1;
        const float* xr = xs + m * XS_LD + half * 128;
        float s = 0.0f;
        #pragma unroll 8
        for (int k = 0; k < 128; ++k) s += xr[k] * xr[k];
        s += __shfl_xor_sync(0xffffffffu, s, 1);
        if (half == 0) rssq_s[m] = s;
    }
    __syncthreads();

    float a_ssq[8];
    #pragma unroll
    for (int i = 0; i < 8; ++i) a_ssq[i] = rssq_s[ty + 16 * i];

    float rbest[8];
    int   ridx[8];
    #pragma unroll
    for (int i = 0; i < 8; ++i) { rbest[i] = -3.4e38f; ridx[i] = 0x7fffffff; }

    for (int p = 0; p < 4; ++p) {
        unsigned long long acc[8][8];
        #pragma unroll
        for (int i = 0; i < 8; ++i)
            #pragma unroll
            for (int j = 0; j < 8; ++j) acc[i][j] = 0ULL;

        for (int kk = 0; kk < 2; ++kk) {
            __syncthreads();
            // load 128-code x 128-k chunk of normalized codebook (L2-hot)
            const float* gc = g_embed_n + (p * BN) * DIM + kk * BK;
            #pragma unroll
            for (int it = 0; it < 16; ++it) {
                int idx = tid + it * 256;      // 0..4095
                int n = idx >> 5, d4 = idx & 31;
                float4 v = *(const float4*)(gc + n * DIM + d4 * 4);
                float2* dst = (float2*)(cs + n * CS_LD + d4 * 4);
                dst[0] = make_float2(v.x, v.y);
                dst[1] = make_float2(v.z, v.w);
            }
            __syncthreads();

            const float* xb = xs + ty * XS_LD + kk * BK;
            const float* cb = cs + tx * CS_LD;
            #pragma unroll 2
            for (int k2 = 0; k2 < 64; ++k2) {
                unsigned long long a[8], b[8];
                #pragma unroll
                for (int i = 0; i < 8; ++i)
                    a[i] = *(const unsigned long long*)(xb + i * 16 * XS_LD + 2 * k2);
                #pragma unroll
                for (int j = 0; j < 8; ++j)
                    b[j] = *(const unsigned long long*)(cb + j * 16 * CS_LD + 2 * k2);
                #pragma unroll
                for (int i = 0; i < 8; ++i)
                    #pragma unroll
                    for (int j = 0; j < 8; ++j)
                        fma2(acc[i][j], a[i], b[j]);
            }
        }

        // per-row argmax over this 128-code panel.
        // Replicate reference rounding: dist = (||x||^2 - 2*dot) + ||e||^2,
        // maximize -dist with first-index tie-break (jnp.argmax semantics).
        #pragma unroll
        for (int i = 0; i < 8; ++i) {
            float bv = -3.4e38f;
            int   bi = 0x7fffffff;
            #pragma unroll
            for (int j = 0; j < 8; ++j) {
                int n  = tx + 16 * j;
                float lo = __uint_as_float((unsigned)(acc[i][j] & 0xffffffffull));
                float hi = __uint_as_float((unsigned)(acc[i][j] >> 32));
                float dot = lo + hi;
                float v = -((a_ssq[i] - 2.0f * dot) + ssq_s[p * BN + n]);
                int gi = p * BN + n;
                if (v > bv || (v == bv && gi < bi)) { bv = v; bi = gi; }
            }
            #pragma unroll
            for (int off = 1; off < 16; off <<= 1) {
                float ov = __shfl_xor_sync(0xffffffffu, bv, off);
                int   oi = __shfl_xor_sync(0xffffffffu, bi, off);
                if (ov > bv || (ov == bv && oi < bi)) { bv = ov; bi = oi; }
            }
            if (bv > rbest[i] || (bv == rbest[i] && bi < ridx[i])) {
                rbest[i] = bv; ridx[i] = bi;
            }
        }
    }

    __syncthreads();
    if (tx == 0) {
        #pragma unroll
        for (int i = 0; i < 8; ++i) {
            int m = ty + 16 * i;
            best_s[m] = ridx[i];
            ind_out[n0 + m] = (float)ridx[i];
        }
    }
    __syncthreads();

    // gather + out + MSE partial. d = tid (coalesced), codebook rows L2-hot.
    float dsum = 0.0f;
    for (int m = 0; m < BM; ++m) {
        int e   = best_s[m];
        float q = g_embed_n[e * DIM + tid];
        float x = xs[m * XS_LD + tid];
        float q1 = x + (q - x);                 // replicate reference fp exactly
        out[(n0 + m) * DIM + tid] = (q + q1) * 0.5f;
        float dd = q - x;
        dsum += dd * dd;
    }
    #pragma unroll
    for (int o = 16; o > 0; o >>= 1) dsum += __shfl_xor_sync(0xffffffffu, dsum, o);
    if ((tid & 31) == 0) red[tid >> 5] = dsum;
    __syncthreads();
    if (tid == 0) {
        float tot = 0.0f;
        #pragma unroll
        for (int k = 0; k < 8; ++k) tot += red[k];
        atomicAdd(&g_diff, tot);
    }
}

// ---------------------------------------------------------------- loss ----
__global__ void final_kernel(float* __restrict__ loss_out) {
    __shared__ float w[8];
    int t = threadIdx.x;
    float v = g_sum[t];
    float s = v * v;
    #pragma unroll
    for (int o = 16; o > 0; o >>= 1) s += __shfl_xor_sync(0xffffffffu, s, o);
    if ((t & 31) == 0) w[t >> 5] = s;
    __syncthreads();
    if (t == 0) {
        float snorm2 = 0.0f;
        #pragma unroll
        for (int k = 0; k < 8; ++k) snorm2 += w[k];
        // entropy = 2*E*sum_i ||e_i||^2 - 2*||sum_i e_i||^2
        float entropy = 2.0f * (float)NEMBED * g_ssqsum - 2.0f * snorm2;
        float diff = g_diff * (1.0f / (float)OUT_ELEMS);
        loss_out[0] = diff - entropy * (1.0f / ((float)NEMBED * (float)NEMBED));
    }
}

// -------------------------------------------------------------- launch ----
extern "C" void kernel_launch(void* const* d_in, const int* in_sizes, int n_in,
                              void* d_out, int out_size) {
    const float* input     = (const float*)d_in[0];
    const float* embedding = (const float*)d_in[1];
    float* out  = (float*)d_out;
    float* loss = out + LOSS_OFF;
    float* ind  = out + IND_OFF;

    cudaFuncSetAttribute(main_kernel,
                         cudaFuncAttributeMaxDynamicSharedMemorySize, SMEM_BYTES);

    init_kernel<<<1, 256>>>();
    normalize_kernel<<<NEMBED, 256>>>(embedding);
    main_kernel<<<NROWS / BM, 256, SMEM_BYTES>>>(input, out, ind);
    final_kernel<<<1, 256>>>(loss);
}

// round 4
// speedup vs baseline: 1.1103x; 1.1103x over previous
#include <cuda_runtime.h>
#include <cstdint>

#define DIM     256
#define NEMBED  512
#define NROWS   131072
#define OUT_ELEMS 33554432
#define LOSS_OFF  33554432
#define IND_OFF   33554433

#define BM 128
#define PANEL 32                 // codes per panel
#define NPANEL (NEMBED / PANEL)  // 16
#define A_LD 260                 // floats per row (256+4): bank(lane)=lane
#define B_LD 260

// smem layout (floats)
#define F_A     0
#define F_BHI   (F_A + BM * A_LD)                 // 33280
#define F_BLO   (F_BHI + PANEL * B_LD)            // +8320
#define F_SSQE  (F_BLO + PANEL * B_LD)            // +8320
#define F_RSSQ  (F_SSQE + NEMBED)
#define F_BEST  (F_RSSQ + BM)
#define F_RED   (F_BEST + BM)
#define SMEM_FLOATS (F_RED + 8)
#define SMEM_BYTES  (SMEM_FLOATS * 4)             // ~204 KB

__device__ float g_embed_n[NEMBED * DIM];
__device__ float g_bhi[NEMBED * DIM];
__device__ float g_blo[NEMBED * DIM];
__device__ float g_ssq[NEMBED];
__device__ float g_sum[DIM];
__device__ float g_ssqsum;
__device__ float g_diff;

__device__ __forceinline__ float tf32_rn(float x) {
    uint32_t u;
    asm("cvt.rna.tf32.f32 %0, %1;" : "=r"(u) : "f"(x));
    return __uint_as_float(u);
}
__device__ __forceinline__ void mma_tf32(float* d,
                                         uint32_t a0, uint32_t a1, uint32_t a2, uint32_t a3,
                                         uint32_t b0, uint32_t b1) {
    asm volatile(
        "mma.sync.aligned.m16n8k8.row.col.f32.tf32.tf32.f32 "
        "{%0,%1,%2,%3}, {%4,%5,%6,%7}, {%8,%9}, {%0,%1,%2,%3};"
        : "+f"(d[0]), "+f"(d[1]), "+f"(d[2]), "+f"(d[3])
        : "r"(a0), "r"(a1), "r"(a2), "r"(a3), "r"(b0), "r"(b1));
}

// ---------------------------------------------------------------- init ----
__global__ void init_kernel() {
    int t = threadIdx.x;
    g_sum[t] = 0.0f;
    if (t == 0) { g_ssqsum = 0.0f; g_diff = 0.0f; }
}

// ---------------------------------------------- normalize + tf32 split ----
__global__ void normalize_kernel(const float* __restrict__ emb) {
    __shared__ float w[8];
    int r = blockIdx.x, t = threadIdx.x;
    float v = emb[r * DIM + t];
    float s = v * v;
    #pragma unroll
    for (int o = 16; o > 0; o >>= 1) s += __shfl_xor_sync(0xffffffffu, s, o);
    if ((t & 31) == 0) w[t >> 5] = s;
    __syncthreads();
    float sum = 0.0f;
    #pragma unroll
    for (int k = 0; k < 8; ++k) sum += w[k];
    float en = __fdiv_rn(v, __fsqrt_rn(sum));
    g_embed_n[r * DIM + t] = en;
    float hi = tf32_rn(en);
    g_bhi[r * DIM + t] = hi;
    g_blo[r * DIM + t] = tf32_rn(en - hi);
    atomicAdd(&g_sum[t], en);

    float s2 = en * en;
    #pragma unroll
    for (int o = 16; o > 0; o >>= 1) s2 += __shfl_xor_sync(0xffffffffu, s2, o);
    __syncthreads();
    if ((t & 31) == 0) w[t >> 5] = s2;
    __syncthreads();
    if (t == 0) {
        float tot = 0.0f;
        #pragma unroll
        for (int k = 0; k < 8; ++k) tot += w[k];
        g_ssq[r] = tot;
        atomicAdd(&g_ssqsum, tot);
    }
}

// ------------------------------------------------------------- main ----
__global__ void __launch_bounds__(256, 1)
main_kernel(const float* __restrict__ input,
            float* __restrict__ out,
            float* __restrict__ ind_out) {
    extern __shared__ float sm[];
    float* xs     = sm + F_A;
    float* bh     = sm + F_BHI;
    float* bl     = sm + F_BLO;
    float* ssq_s  = sm + F_SSQE;
    float* rssq_s = sm + F_RSSQ;
    int*   best_s = (int*)(sm + F_BEST);
    float* red    = sm + F_RED;

    const int tid = threadIdx.x;
    const int wid = tid >> 5;
    const int lid = tid & 31;
    const int lq  = lid >> 2;          // 0..7
    const int lr  = lid & 3;           // 0..3
    const size_t n0 = (size_t)blockIdx.x * BM;

    // load 128x256 input tile (read once from HBM); reused by epilogue
    #pragma unroll
    for (int i = 0; i < 32; ++i) {
        int slot = tid + i * 256;          // 0..8191
        int m = slot >> 6, c4 = slot & 63;
        float4 v = *(const float4*)(input + (n0 + m) * DIM + c4 * 4);
        *(float4*)(xs + m * A_LD + c4 * 4) = v;
    }
    ssq_s[tid]       = g_ssq[tid];
    ssq_s[tid + 256] = g_ssq[tid + 256];
    __syncthreads();

    // per-row ||x||^2 (deterministic fixed order, matches R2 passing kernel)
    {
        int m = tid >> 1, half = tid & 1;
        const float* xr = xs + m * A_LD + half * 128;
        float s = 0.0f;
        #pragma unroll 8
        for (int k = 0; k < 128; ++k) s += xr[k] * xr[k];
        s += __shfl_xor_sync(0xffffffffu, s, 1);
        if (half == 0) rssq_s[m] = s;
    }
    __syncthreads();

    const int r0 = wid * 16 + lq;          // this thread's row pair: r0, r0+8
    const float a_ssq0 = rssq_s[r0];
    const float a_ssq1 = rssq_s[r0 + 8];

    // running argmax state for rows r0, r0+8
    float bv0 = -3.4e38f, bv1 = -3.4e38f;
    int   bi0 = 0x7fffffff, bi1 = 0x7fffffff;

    const float* arow0 = xs + r0 * A_LD;
    const float* arow1 = xs + (r0 + 8) * A_LD;

    for (int p = 0; p < NPANEL; ++p) {
        __syncthreads();
        // load 32-code panel hi+lo (full K=256) from L2
        const float* gh = g_bhi + (p * PANEL) * DIM;
        const float* gl = g_blo + (p * PANEL) * DIM;
        #pragma unroll
        for (int i = 0; i < 8; ++i) {
            int slot = tid + i * 256;      // 0..2047
            int r = slot >> 6, c4 = slot & 63;
            *(float4*)(bh + r * B_LD + c4 * 4) = *(const float4*)(gh + r * DIM + c4 * 4);
            *(float4*)(bl + r * B_LD + c4 * 4) = *(const float4*)(gl + r * DIM + c4 * 4);
        }
        __syncthreads();

        float acc[4][4];
        #pragma unroll
        for (int j = 0; j < 4; ++j)
            #pragma unroll
            for (int q = 0; q < 4; ++q) acc[j][q] = 0.0f;

        #pragma unroll 2
        for (int kt = 0; kt < 32; ++kt) {
            const int c = kt * 8 + lr;
            // A fragment: rows r0/r0+8, cols c, c+4; split to tf32 hi/lo
            float x0 = arow0[c], x1 = arow1[c], x2 = arow0[c + 4], x3 = arow1[c + 4];
            float h0 = tf32_rn(x0), h1 = tf32_rn(x1), h2 = tf32_rn(x2), h3 = tf32_rn(x3);
            uint32_t ah0 = __float_as_uint(h0), ah1 = __float_as_uint(h1);
            uint32_t ah2 = __float_as_uint(h2), ah3 = __float_as_uint(h3);
            uint32_t al0 = __float_as_uint(tf32_rn(x0 - h0));
            uint32_t al1 = __float_as_uint(tf32_rn(x1 - h1));
            uint32_t al2 = __float_as_uint(tf32_rn(x2 - h2));
            uint32_t al3 = __float_as_uint(tf32_rn(x3 - h3));
            #pragma unroll
            for (int j = 0; j < 4; ++j) {
                const int n = j * 8 + lq;
                uint32_t bh0 = __float_as_uint(bh[n * B_LD + c]);
                uint32_t bh1 = __float_as_uint(bh[n * B_LD + c + 4]);
                uint32_t bl0 = __float_as_uint(bl[n * B_LD + c]);
                uint32_t bl1 = __float_as_uint(bl[n * B_LD + c + 4]);
                mma_tf32(acc[j], ah0, ah1, ah2, ah3, bh0, bh1);  // hi*hi
                mma_tf32(acc[j], ah0, ah1, ah2, ah3, bl0, bl1);  // hi*lo
                mma_tf32(acc[j], al0, al1, al2, al3, bh0, bh1);  // lo*hi
            }
        }

        // fold panel into running argmax (reference rounding, first-index ties)
        #pragma unroll
        for (int j = 0; j < 4; ++j) {
            #pragma unroll
            for (int e = 0; e < 2; ++e) {
                int n = p * PANEL + j * 8 + 2 * lr + e;
                float se = ssq_s[n];
                float v0 = -((a_ssq0 - 2.0f * acc[j][e]) + se);
                float v1 = -((a_ssq1 - 2.0f * acc[j][2 + e]) + se);
                if (v0 > bv0 || (v0 == bv0 && n < bi0)) { bv0 = v0; bi0 = n; }
                if (v1 > bv1 || (v1 == bv1 && n < bi1)) { bv1 = v1; bi1 = n; }
            }
        }
    }

    // reduce argmax across the 4 lanes sharing each row (lanes lq*4..lq*4+3)
    #pragma unroll
    for (int off = 1; off < 4; off <<= 1) {
        float o0 = __shfl_xor_sync(0xffffffffu, bv0, off);
        int   i0 = __shfl_xor_sync(0xffffffffu, bi0, off);
        if (o0 > bv0 || (o0 == bv0 && i0 < bi0)) { bv0 = o0; bi0 = i0; }
        float o1 = __shfl_xor_sync(0xffffffffu, bv1, off);
        int   i1 = __shfl_xor_sync(0xffffffffu, bi1, off);
        if (o1 > bv1 || (o1 == bv1 && i1 < bi1)) { bv1 = o1; bi1 = i1; }
    }
    if (lr == 0) {
        best_s[r0]     = bi0;
        best_s[r0 + 8] = bi1;
        ind_out[n0 + r0]     = (float)bi0;
        ind_out[n0 + r0 + 8] = (float)bi1;
    }
    __syncthreads();

    // ---- gather + out + MSE (col = tid, input from smem, codebook L2-hot) ----
    float dsum = 0.0f;
    for (int m = 0; m < BM; ++m) {
        int e   = best_s[m];
        float q = g_embed_n[e * DIM + tid];
        float x = xs[m * A_LD + tid];
        float q1 = x + (q - x);
        out[(n0 + m) * DIM + tid] = (q + q1) * 0.5f;
        float dd = q - x;
        dsum += dd * dd;
    }
    #pragma unroll
    for (int o = 16; o > 0; o >>= 1) dsum += __shfl_xor_sync(0xffffffffu, dsum, o);
    if ((tid & 31) == 0) red[tid >> 5] = dsum;
    __syncthreads();
    if (tid == 0) {
        float tot = 0.0f;
        #pragma unroll
        for (int k = 0; k < 8; ++k) tot += red[k];
        atomicAdd(&g_diff, tot);
    }
}

// ---------------------------------------------------------------- loss ----
__global__ void final_kernel(float* __restrict__ loss_out) {
    __shared__ float w[8];
    int t = threadIdx.x;
    float v = g_sum[t];
    float s = v * v;
    #pragma unroll
    for (int o = 16; o > 0; o >>= 1) s += __shfl_xor_sync(0xffffffffu, s, o);
    if ((t & 31) == 0) w[t >> 5] = s;
    __syncthreads();
    if (t == 0) {
        float snorm2 = 0.0f;
        #pragma unroll
        for (int k = 0; k < 8; ++k) snorm2 += w[k];
        float entropy = 2.0f * (float)NEMBED * g_ssqsum - 2.0f * snorm2;
        float diff = g_diff * (1.0f / (float)OUT_ELEMS);
        loss_out[0] = diff - entropy * (1.0f / ((float)NEMBED * (float)NEMBED));
    }
}

// -------------------------------------------------------------- launch ----
extern "C" void kernel_launch(void* const* d_in, const int* in_sizes, int n_in,
                              void* d_out, int out_size) {
    const float* input     = (const float*)d_in[0];
    const float* embedding = (const float*)d_in[1];
    float* out  = (float*)d_out;
    float* loss = out + LOSS_OFF;
    float* ind  = out + IND_OFF;

    cudaFuncSetAttribute(main_kernel,
                         cudaFuncAttributeMaxDynamicSharedMemorySize, SMEM_BYTES);

    init_kernel<<<1, 256>>>();
    normalize_kernel<<<NEMBED, 256>>>(embedding);
    main_kernel<<<NROWS / BM, 256, SMEM_BYTES>>>(input, out, ind);
    final_kernel<<<1, 256>>>(loss);
}

// round 5
// speedup vs baseline: 1.5119x; 1.3617x over previous
#include <cuda_runtime.h>
#include <cuda_fp16.h>
#include <cstdint>

#define DIM     256
#define NEMBED  512
#define NROWS   131072
#define OUT_ELEMS 33554432
#define LOSS_OFF  33554432
#define IND_OFF   33554433

#define BM 128
#define PANEL 32
#define NPANEL (NEMBED / PANEL)   // 16
#define KLD 264                   // halves per row: banks (4*lq+lr) conflict-free
#define SCALE 2048.0f             // 2^11
#define INV_SCALE2 2.38418579e-07f // 0x1p-22f exact

// smem byte offsets
#define OFF_AHI  0
#define OFF_ALO  (OFF_AHI + BM * KLD * 2)        // 67584
#define OFF_BH   (OFF_ALO + BM * KLD * 2)        // 135168
#define OFF_BL   (OFF_BH + PANEL * KLD * 2)      // 152064
#define OFF_SSQ  (OFF_BL + PANEL * KLD * 2)      // 168960
#define OFF_RSSQ (OFF_SSQ + NEMBED * 4)          // 171008
#define OFF_BEST (OFF_RSSQ + BM * 4)             // 171520
#define OFF_RED  (OFF_BEST + BM * 4)             // 172032
#define SMEM_BYTES (OFF_RED + 32)                // 172064

__device__ float  g_embed_n[NEMBED * DIM];
__device__ __half g_bh16[NEMBED * DIM];
__device__ __half g_bl16[NEMBED * DIM];
__device__ float  g_ssq[NEMBED];
__device__ float  g_sum[DIM];
__device__ float  g_ssqsum;
__device__ float  g_diff;

__device__ __forceinline__ void mma_f16(float* d, uint32_t a0, uint32_t a1,
                                        uint32_t a2, uint32_t a3,
                                        uint32_t b0, uint32_t b1) {
    asm volatile(
        "mma.sync.aligned.m16n8k16.row.col.f32.f16.f16.f32 "
        "{%0,%1,%2,%3}, {%4,%5,%6,%7}, {%8,%9}, {%0,%1,%2,%3};"
        : "+f"(d[0]), "+f"(d[1]), "+f"(d[2]), "+f"(d[3])
        : "r"(a0), "r"(a1), "r"(a2), "r"(a3), "r"(b0), "r"(b1));
}

// ---------------------------------------------------------------- init ----
__global__ void init_kernel() {
    int t = threadIdx.x;
    g_sum[t] = 0.0f;
    if (t == 0) { g_ssqsum = 0.0f; g_diff = 0.0f; }
}

// ------------------------------------- normalize + fp16 split (scaled) ----
__global__ void normalize_kernel(const float* __restrict__ emb) {
    __shared__ float w[8];
    int r = blockIdx.x, t = threadIdx.x;
    float v = emb[r * DIM + t];
    float s = v * v;
    #pragma unroll
    for (int o = 16; o > 0; o >>= 1) s += __shfl_xor_sync(0xffffffffu, s, o);
    if ((t & 31) == 0) w[t >> 5] = s;
    __syncthreads();
    float sum = 0.0f;
    #pragma unroll
    for (int k = 0; k < 8; ++k) sum += w[k];
    float en = __fdiv_rn(v, __fsqrt_rn(sum));
    g_embed_n[r * DIM + t] = en;
    float sc = en * SCALE;
    __half h = __float2half_rn(sc);
    g_bh16[r * DIM + t] = h;
    g_bl16[r * DIM + t] = __float2half_rn(sc - __half2float(h));
    atomicAdd(&g_sum[t], en);

    float s2 = en * en;
    #pragma unroll
    for (int o = 16; o > 0; o >>= 1) s2 += __shfl_xor_sync(0xffffffffu, s2, o);
    __syncthreads();
    if ((t & 31) == 0) w[t >> 5] = s2;
    __syncthreads();
    if (t == 0) {
        float tot = 0.0f;
        #pragma unroll
        for (int k = 0; k < 8; ++k) tot += w[k];
        g_ssq[r] = tot;
        atomicAdd(&g_ssqsum, tot);
    }
}

// ------------------------------------------------------------- main ----
__global__ void __launch_bounds__(256, 1)
main_kernel(const float* __restrict__ input,
            float* __restrict__ out,
            float* __restrict__ ind_out) {
    extern __shared__ char sm[];
    __half* ahi   = (__half*)(sm + OFF_AHI);
    __half* alo   = (__half*)(sm + OFF_ALO);
    __half* bh    = (__half*)(sm + OFF_BH);
    __half* bl    = (__half*)(sm + OFF_BL);
    float*  ssq_s = (float*)(sm + OFF_SSQ);
    float*  rssq_s= (float*)(sm + OFF_RSSQ);
    int*    best_s= (int*)(sm + OFF_BEST);
    float*  red   = (float*)(sm + OFF_RED);

    const int tid = threadIdx.x;
    const int wid = tid >> 5;
    const int lid = tid & 31;
    const int lq  = lid >> 2;      // 0..7
    const int lr  = lid & 3;       // 0..3
    const size_t n0 = (size_t)blockIdx.x * BM;

    // ---- phase 1: load input tile, scale by 2^11, split to fp16 hi/lo ----
    #pragma unroll
    for (int i = 0; i < 32; ++i) {
        int slot = tid + i * 256;            // 0..8191
        int m = slot >> 6, c4 = slot & 63;   // row, float4-col
        float4 v = *(const float4*)(input + (n0 + m) * DIM + c4 * 4);
        float sx = v.x * SCALE, sy = v.y * SCALE, sz = v.z * SCALE, sw = v.w * SCALE;
        __half hx = __float2half_rn(sx), hy = __float2half_rn(sy);
        __half hz = __float2half_rn(sz), hw = __float2half_rn(sw);
        __half lx = __float2half_rn(sx - __half2float(hx));
        __half ly = __float2half_rn(sy - __half2float(hy));
        __half lz = __float2half_rn(sz - __half2float(hz));
        __half lw = __float2half_rn(sw - __half2float(hw));
        int ho = m * KLD + c4 * 4;
        *(__half2*)(ahi + ho)     = __halves2half2(hx, hy);
        *(__half2*)(ahi + ho + 2) = __halves2half2(hz, hw);
        *(__half2*)(alo + ho)     = __halves2half2(lx, ly);
        *(__half2*)(alo + ho + 2) = __halves2half2(lz, lw);
    }
    ssq_s[tid]       = g_ssq[tid];
    ssq_s[tid + 256] = g_ssq[tid + 256];

    // ---- per-row ||x||^2 (same arithmetic order as passing R2/R4) ----
    {
        int m = tid >> 1, half = tid & 1;
        const float* xr = input + (n0 + m) * DIM + half * 128;
        float s = 0.0f;
        #pragma unroll 8
        for (int k = 0; k < 128; ++k) s += xr[k] * xr[k];
        s += __shfl_xor_sync(0xffffffffu, s, 1);
        if (half == 0) rssq_s[m] = s;
    }

    const int r0 = wid * 16 + lq;
    float bv0 = -3.4e38f, bv1 = -3.4e38f;
    int   bi0 = 0x7fffffff, bi1 = 0x7fffffff;

    const int abase = (wid * 16 + lq) * KLD + 2 * lr;   // half offset

    for (int p = 0; p < NPANEL; ++p) {
        __syncthreads();
        // load 32-code panel hi+lo from global (L2-hot), uint4 = 8 halves
        {
            const __half* gh = g_bh16 + (p * PANEL) * DIM;
            const __half* gl = g_bl16 + (p * PANEL) * DIM;
            #pragma unroll
            for (int i = 0; i < 4; ++i) {
                int slot = tid + i * 256;        // 0..1023
                int r = slot >> 5, c8 = slot & 31;
                *(uint4*)(bh + r * KLD + c8 * 8) = *(const uint4*)(gh + r * DIM + c8 * 8);
                *(uint4*)(bl + r * KLD + c8 * 8) = *(const uint4*)(gl + r * DIM + c8 * 8);
            }
        }
        __syncthreads();

        float a0[4][4], a1[4][4], a2[4][4];    // (ahi,bh) (ahi,bl) (alo,bh)
        #pragma unroll
        for (int j = 0; j < 4; ++j)
            #pragma unroll
            for (int q = 0; q < 4; ++q) { a0[j][q] = 0.f; a1[j][q] = 0.f; a2[j][q] = 0.f; }

        #pragma unroll 4
        for (int kt = 0; kt < 16; ++kt) {
            const int ko = kt * 16;
            const __half* ah = ahi + abase + ko;
            const __half* al = alo + abase + ko;
            uint32_t Ah0 = *(const uint32_t*)(ah);
            uint32_t Ah1 = *(const uint32_t*)(ah + 8 * KLD);
            uint32_t Ah2 = *(const uint32_t*)(ah + 8);
            uint32_t Ah3 = *(const uint32_t*)(ah + 8 * KLD + 8);
            uint32_t Al0 = *(const uint32_t*)(al);
            uint32_t Al1 = *(const uint32_t*)(al + 8 * KLD);
            uint32_t Al2 = *(const uint32_t*)(al + 8);
            uint32_t Al3 = *(const uint32_t*)(al + 8 * KLD + 8);
            #pragma unroll
            for (int j = 0; j < 4; ++j) {
                const int bb = (8 * j + lq) * KLD + 2 * lr + ko;
                uint32_t Bh0 = *(const uint32_t*)(bh + bb);
                uint32_t Bh1 = *(const uint32_t*)(bh + bb + 8);
                uint32_t Bl0 = *(const uint32_t*)(bl + bb);
                uint32_t Bl1 = *(const uint32_t*)(bl + bb + 8);
                mma_f16(a0[j], Ah0, Ah1, Ah2, Ah3, Bh0, Bh1);
                mma_f16(a1[j], Ah0, Ah1, Ah2, Ah3, Bl0, Bl1);
                mma_f16(a2[j], Al0, Al1, Al2, Al3, Bh0, Bh1);
            }
        }

        // fold panel into running argmax (reference rounding, first-index ties)
        const float assq0 = rssq_s[r0];
        const float assq1 = rssq_s[r0 + 8];
        #pragma unroll
        for (int j = 0; j < 4; ++j) {
            #pragma unroll
            for (int e = 0; e < 2; ++e) {
                int n = p * PANEL + 8 * j + 2 * lr + e;
                float se = ssq_s[n];
                float d0 = (a0[j][e] + a1[j][e] + a2[j][e]) * INV_SCALE2;
                float d1 = (a0[j][2 + e] + a1[j][2 + e] + a2[j][2 + e]) * INV_SCALE2;
                float v0 = -((assq0 - 2.0f * d0) + se);
                float v1 = -((assq1 - 2.0f * d1) + se);
                if (v0 > bv0 || (v0 == bv0 && n < bi0)) { bv0 = v0; bi0 = n; }
                if (v1 > bv1 || (v1 == bv1 && n < bi1)) { bv1 = v1; bi1 = n; }
            }
        }
    }

    // reduce across the 4 lanes sharing each row
    #pragma unroll
    for (int off = 1; off < 4; off <<= 1) {
        float o0 = __shfl_xor_sync(0xffffffffu, bv0, off);
        int   i0 = __shfl_xor_sync(0xffffffffu, bi0, off);
        if (o0 > bv0 || (o0 == bv0 && i0 < bi0)) { bv0 = o0; bi0 = i0; }
        float o1 = __shfl_xor_sync(0xffffffffu, bv1, off);
        int   i1 = __shfl_xor_sync(0xffffffffu, bi1, off);
        if (o1 > bv1 || (o1 == bv1 && i1 < bi1)) { bv1 = o1; bi1 = i1; }
    }
    if (lr == 0) {
        best_s[r0]     = bi0;
        best_s[r0 + 8] = bi1;
        ind_out[n0 + r0]     = (float)bi0;
        ind_out[n0 + r0 + 8] = (float)bi1;
    }
    __syncthreads();

    // ---- gather + out + MSE (col = tid; input re-read, L1/L2-hot) ----
    float dsum = 0.0f;
    for (int m = 0; m < BM; ++m) {
        int e   = best_s[m];
        float q = g_embed_n[e * DIM + tid];
        float x = input[(n0 + m) * DIM + tid];
        float q1 = x + (q - x);
        out[(n0 + m) * DIM + tid] = (q + q1) * 0.5f;
        float dd = q - x;
        dsum += dd * dd;
    }
    #pragma unroll
    for (int o = 16; o > 0; o >>= 1) dsum += __shfl_xor_sync(0xffffffffu, dsum, o);
    if ((tid & 31) == 0) red[tid >> 5] = dsum;
    __syncthreads();
    if (tid == 0) {
        float tot = 0.0f;
        #pragma unroll
        for (int k = 0; k < 8; ++k) tot += red[k];
        atomicAdd(&g_diff, tot);
    }
}

// ---------------------------------------------------------------- loss ----
__global__ void final_kernel(float* __restrict__ loss_out) {
    __shared__ float w[8];
    int t = threadIdx.x;
    float v = g_sum[t];
    float s = v * v;
    #pragma unroll
    for (int o = 16; o > 0; o >>= 1) s += __shfl_xor_sync(0xffffffffu, s, o);
    if ((t & 31) == 0) w[t >> 5] = s;
    __syncthreads();
    if (t == 0) {
        float snorm2 = 0.0f;
        #pragma unroll
        for (int k = 0; k < 8; ++k) snorm2 += w[k];
        float entropy = 2.0f * (float)NEMBED * g_ssqsum - 2.0f * snorm2;
        float diff = g_diff * (1.0f / (float)OUT_ELEMS);
        loss_out[0] = diff - entropy * (1.0f / ((float)NEMBED * (float)NEMBED));
    }
}

// -------------------------------------------------------------- launch ----
extern "C" void kernel_launch(void* const* d_in, const int* in_sizes, int n_in,
                              void* d_out, int out_size) {
    const float* input     = (const float*)d_in[0];
    const float* embedding = (const float*)d_in[1];
    float* out  = (float*)d_out;
    float* loss = out + LOSS_OFF;
    float* ind  = out + IND_OFF;

    cudaFuncSetAttribute(main_kernel,
                         cudaFuncAttributeMaxDynamicSharedMemorySize, SMEM_BYTES);

    init_kernel<<<1, 256>>>();
    normalize_kernel<<<NEMBED, 256>>>(embedding);
    main_kernel<<<NROWS / BM, 256, SMEM_BYTES>>>(input, out, ind);
    final_kernel<<<1, 256>>>(loss);
}

// round 6
// speedup vs baseline: 1.5498x; 1.0251x over previous
#include <cuda_runtime.h>
#include <cuda_fp16.h>
#include <cstdint>

#define DIM     256
#define NEMBED  512
#define NROWS   131072
#define OUT_ELEMS 33554432
#define LOSS_OFF  33554432
#define IND_OFF   33554433

#define BM 128
#define PANEL 32
#define NPANEL (NEMBED / PANEL)   // 16
#define KLD 264                   // halves per row; 528B stride = 4 banks mod 32
#define SCALE 2048.0f             // 2^11
#define INV_SCALE2 2.38418579e-07f // 2^-22 exact

#define ROWB (KLD * 2)            // 528 bytes per row
#define OFF_AHI  0
#define OFF_ALO  (OFF_AHI + BM * ROWB)       // 67584
#define OFF_B    (OFF_ALO + BM * ROWB)       // 135168
#define BSTAGE_H (PANEL * ROWB)              // 16896 (hi block)
#define BSTAGE   (2 * BSTAGE_H)              // 33792 (hi+lo per stage)
#define OFF_SSQ  (OFF_B + 2 * BSTAGE)        // 202752
#define OFF_RSSQ (OFF_SSQ + NEMBED * 4)
#define OFF_BEST (OFF_RSSQ + BM * 4)
#define OFF_RED  (OFF_BEST + BM * 4)
#define SMEM_BYTES (OFF_RED + 32)            // ~205888

__device__ float  g_embed_n[NEMBED * DIM];
__device__ __half g_bh16[NEMBED * DIM];
__device__ __half g_bl16[NEMBED * DIM];
__device__ float  g_ssq[NEMBED];
__device__ float  g_sum[DIM];
__device__ float  g_ssqsum;
__device__ float  g_diff;

__device__ __forceinline__ uint32_t smem_u32(const void* p) {
    uint32_t a;
    asm("{ .reg .u64 t; cvta.to.shared.u64 t, %1; cvt.u32.u64 %0, t; }" : "=r"(a) : "l"(p));
    return a;
}
__device__ __forceinline__ void mma_f16(float* d, uint32_t a0, uint32_t a1,
                                        uint32_t a2, uint32_t a3,
                                        uint32_t b0, uint32_t b1) {
    asm volatile(
        "mma.sync.aligned.m16n8k16.row.col.f32.f16.f16.f32 "
        "{%0,%1,%2,%3}, {%4,%5,%6,%7}, {%8,%9}, {%0,%1,%2,%3};"
        : "+f"(d[0]), "+f"(d[1]), "+f"(d[2]), "+f"(d[3])
        : "r"(a0), "r"(a1), "r"(a2), "r"(a3), "r"(b0), "r"(b1));
}
__device__ __forceinline__ void ldsm4(uint32_t& r0, uint32_t& r1,
                                      uint32_t& r2, uint32_t& r3, uint32_t addr) {
    asm volatile("ldmatrix.sync.aligned.m8n8.x4.shared.b16 {%0,%1,%2,%3}, [%4];"
                 : "=r"(r0), "=r"(r1), "=r"(r2), "=r"(r3) : "r"(addr));
}
__device__ __forceinline__ void cp16(uint32_t dst, const void* src) {
    asm volatile("cp.async.cg.shared.global [%0], [%1], 16;" :: "r"(dst), "l"(src) : "memory");
}
#define CP_COMMIT() asm volatile("cp.async.commit_group;" ::: "memory")
#define CP_WAIT0()  asm volatile("cp.async.wait_group 0;" ::: "memory")

// ---------------------------------------------------------------- init ----
__global__ void init_kernel() {
    int t = threadIdx.x;
    g_sum[t] = 0.0f;
    if (t == 0) { g_ssqsum = 0.0f; g_diff = 0.0f; }
}

// ------------------------------------- normalize + fp16 split (scaled) ----
__global__ void normalize_kernel(const float* __restrict__ emb) {
    __shared__ float w[8];
    int r = blockIdx.x, t = threadIdx.x;
    float v = emb[r * DIM + t];
    float s = v * v;
    #pragma unroll
    for (int o = 16; o > 0; o >>= 1) s += __shfl_xor_sync(0xffffffffu, s, o);
    if ((t & 31) == 0) w[t >> 5] = s;
    __syncthreads();
    float sum = 0.0f;
    #pragma unroll
    for (int k = 0; k < 8; ++k) sum += w[k];
    float en = __fdiv_rn(v, __fsqrt_rn(sum));
    g_embed_n[r * DIM + t] = en;
    float sc = en * SCALE;
    __half h = __float2half_rn(sc);
    g_bh16[r * DIM + t] = h;
    g_bl16[r * DIM + t] = __float2half_rn(sc - __half2float(h));
    atomicAdd(&g_sum[t], en);

    float s2 = en * en;
    #pragma unroll
    for (int o = 16; o > 0; o >>= 1) s2 += __shfl_xor_sync(0xffffffffu, s2, o);
    __syncthreads();
    if ((t & 31) == 0) w[t >> 5] = s2;
    __syncthreads();
    if (t == 0) {
        float tot = 0.0f;
        #pragma unroll
        for (int k = 0; k < 8; ++k) tot += w[k];
        g_ssq[r] = tot;
        atomicAdd(&g_ssqsum, tot);
    }
}

// ------------------------------------------------------------- main ----
__global__ void __launch_bounds__(256, 1)
main_kernel(const float* __restrict__ input,
            float* __restrict__ out,
            float* __restrict__ ind_out) {
    extern __shared__ char sm[];
    const uint32_t smb = smem_u32(sm);
    __half* ahi   = (__half*)(sm + OFF_AHI);
    __half* alo   = (__half*)(sm + OFF_ALO);
    float*  ssq_s = (float*)(sm + OFF_SSQ);
    float*  rssq_s= (float*)(sm + OFF_RSSQ);
    int*    best_s= (int*)(sm + OFF_BEST);
    float*  red   = (float*)(sm + OFF_RED);

    const int tid = threadIdx.x;
    const int wid = tid >> 5;
    const int lid = tid & 31;
    const int lq  = lid >> 2;
    const int lr  = lid & 3;
    const size_t n0 = (size_t)blockIdx.x * BM;

    // ---- prefetch B panel 0 into stage 0 (overlaps A split) ----
    {
        #pragma unroll
        for (int i = 0; i < 8; ++i) {
            int c = tid + i * 256;               // 0..2047
            int half = c >> 10;                  // 0=hi, 1=lo
            int r = (c >> 5) & 31, ch = c & 31;
            const __half* src = (half ? g_bl16 : g_bh16) + r * DIM + ch * 8;
            cp16(smb + OFF_B + half * BSTAGE_H + r * ROWB + ch * 16, src);
        }
        CP_COMMIT();
    }

    // ---- load input tile, scale by 2^11, split to fp16 hi/lo ----
    #pragma unroll
    for (int i = 0; i < 32; ++i) {
        int slot = tid + i * 256;
        int m = slot >> 6, c4 = slot & 63;
        float4 v = *(const float4*)(input + (n0 + m) * DIM + c4 * 4);
        float sx = v.x * SCALE, sy = v.y * SCALE, sz = v.z * SCALE, sw = v.w * SCALE;
        __half hx = __float2half_rn(sx), hy = __float2half_rn(sy);
        __half hz = __float2half_rn(sz), hw = __float2half_rn(sw);
        __half lx = __float2half_rn(sx - __half2float(hx));
        __half ly = __float2half_rn(sy - __half2float(hy));
        __half lz = __float2half_rn(sz - __half2float(hz));
        __half lw = __float2half_rn(sw - __half2float(hw));
        int ho = m * KLD + c4 * 4;
        *(__half2*)(ahi + ho)     = __halves2half2(hx, hy);
        *(__half2*)(ahi + ho + 2) = __halves2half2(hz, hw);
        *(__half2*)(alo + ho)     = __halves2half2(lx, ly);
        *(__half2*)(alo + ho + 2) = __halves2half2(lz, lw);
    }
    ssq_s[tid]       = g_ssq[tid];
    ssq_s[tid + 256] = g_ssq[tid + 256];

    // ---- per-row ||x||^2 (same arithmetic order as passing kernels) ----
    {
        int m = tid >> 1, half = tid & 1;
        const float* xr = input + (n0 + m) * DIM + half * 128;
        float s = 0.0f;
        #pragma unroll 8
        for (int k = 0; k < 128; ++k) s += xr[k] * xr[k];
        s += __shfl_xor_sync(0xffffffffu, s, 1);
        if (half == 0) rssq_s[m] = s;
    }

    // ---- per-lane ldmatrix addresses ----
    const int rowin = lid & 7;
    const int mi    = lid >> 3;              // matrix index 0..3
    const int aRow  = wid * 16 + rowin + 8 * (mi & 1);
    const uint32_t aHiA = smb + OFF_AHI + (uint32_t)(aRow * ROWB + (mi >> 1) * 16);
    const uint32_t aLoA = aHiA + (OFF_ALO - OFF_AHI);
    // B pair t covers n8 tiles j=2t,2t+1: matrices (j0,k0)(j0,k8)(j1,k0)(j1,k8)
    const uint32_t bOff0 = (uint32_t)((8 * (0 + (mi >> 1)) + rowin) * ROWB + (mi & 1) * 16);
    const uint32_t bOff1 = (uint32_t)((8 * (2 + (mi >> 1)) + rowin) * ROWB + (mi & 1) * 16);

    const int r0 = wid * 16 + lq;
    float bv0 = -3.4e38f, bv1 = -3.4e38f;
    int   bi0 = 0x7fffffff, bi1 = 0x7fffffff;

    for (int p = 0; p < NPANEL; ++p) {
        CP_WAIT0();
        __syncthreads();
        // prefetch next panel into the other stage (safe: all warps past prior reads)
        if (p + 1 < NPANEL) {
            const int np = p + 1, st = np & 1;
            #pragma unroll
            for (int i = 0; i < 8; ++i) {
                int c = tid + i * 256;
                int half = c >> 10;
                int r = (c >> 5) & 31, ch = c & 31;
                const __half* src = (half ? g_bl16 : g_bh16) + (np * PANEL + r) * DIM + ch * 8;
                cp16(smb + OFF_B + st * BSTAGE + half * BSTAGE_H + r * ROWB + ch * 16, src);
            }
            CP_COMMIT();
        }

        const uint32_t sbh = smb + OFF_B + (p & 1) * BSTAGE;
        const uint32_t sbl = sbh + BSTAGE_H;

        float a0[4][4], a1[4][4], a2[4][4];
        #pragma unroll
        for (int j = 0; j < 4; ++j)
            #pragma unroll
            for (int q = 0; q < 4; ++q) { a0[j][q] = 0.f; a1[j][q] = 0.f; a2[j][q] = 0.f; }

        #pragma unroll 4
        for (int kt = 0; kt < 16; ++kt) {
            const uint32_t ka = kt * 32;
            uint32_t Ah0, Ah1, Ah2, Ah3, Al0, Al1, Al2, Al3;
            ldsm4(Ah0, Ah1, Ah2, Ah3, aHiA + ka);
            ldsm4(Al0, Al1, Al2, Al3, aLoA + ka);
            uint32_t Bh[8], Bl[8];
            ldsm4(Bh[0], Bh[1], Bh[2], Bh[3], sbh + bOff0 + ka);   // j0,j1
            ldsm4(Bh[4], Bh[5], Bh[6], Bh[7], sbh + bOff1 + ka);   // j2,j3
            ldsm4(Bl[0], Bl[1], Bl[2], Bl[3], sbl + bOff0 + ka);
            ldsm4(Bl[4], Bl[5], Bl[6], Bl[7], sbl + bOff1 + ka);
            #pragma unroll
            for (int j = 0; j < 4; ++j) {
                mma_f16(a0[j], Ah0, Ah1, Ah2, Ah3, Bh[2 * j], Bh[2 * j + 1]);
                mma_f16(a1[j], Ah0, Ah1, Ah2, Ah3, Bl[2 * j], Bl[2 * j + 1]);
                mma_f16(a2[j], Al0, Al1, Al2, Al3, Bh[2 * j], Bh[2 * j + 1]);
            }
        }

        // fold panel into running argmax (reference rounding, first-index ties)
        const float assq0 = rssq_s[r0];
        const float assq1 = rssq_s[r0 + 8];
        #pragma unroll
        for (int j = 0; j < 4; ++j) {
            #pragma unroll
            for (int e = 0; e < 2; ++e) {
                int n = p * PANEL + 8 * j + 2 * lr + e;
                float se = ssq_s[n];
                float d0 = (a0[j][e] + a1[j][e] + a2[j][e]) * INV_SCALE2;
                float d1 = (a0[j][2 + e] + a1[j][2 + e] + a2[j][2 + e]) * INV_SCALE2;
                float v0 = -((assq0 - 2.0f * d0) + se);
                float v1 = -((assq1 - 2.0f * d1) + se);
                if (v0 > bv0 || (v0 == bv0 && n < bi0)) { bv0 = v0; bi0 = n; }
                if (v1 > bv1 || (v1 == bv1 && n < bi1)) { bv1 = v1; bi1 = n; }
            }
        }
    }

    // reduce across the 4 lanes sharing each row
    #pragma unroll
    for (int off = 1; off < 4; off <<= 1) {
        float o0 = __shfl_xor_sync(0xffffffffu, bv0, off);
        int   i0 = __shfl_xor_sync(0xffffffffu, bi0, off);
        if (o0 > bv0 || (o0 == bv0 && i0 < bi0)) { bv0 = o0; bi0 = i0; }
        float o1 = __shfl_xor_sync(0xffffffffu, bv1, off);
        int   i1 = __shfl_xor_sync(0xffffffffu, bi1, off);
        if (o1 > bv1 || (o1 == bv1 && i1 < bi1)) { bv1 = o1; bi1 = i1; }
    }
    if (lr == 0) {
        best_s[r0]     = bi0;
        best_s[r0 + 8] = bi1;
        ind_out[n0 + r0]     = (float)bi0;
        ind_out[n0 + r0 + 8] = (float)bi1;
    }
    __syncthreads();

    // ---- gather + out + MSE (col = tid; input re-read, L2-hot) ----
    float dsum = 0.0f;
    for (int m = 0; m < BM; ++m) {
        int e   = best_s[m];
        float q = g_embed_n[e * DIM + tid];
        float x = input[(n0 + m) * DIM + tid];
        float q1 = x + (q - x);
        out[(n0 + m) * DIM + tid] = (q + q1) * 0.5f;
        float dd = q - x;
        dsum += dd * dd;
    }
    #pragma unroll
    for (int o = 16; o > 0; o >>= 1) dsum += __shfl_xor_sync(0xffffffffu, dsum, o);
    if ((tid & 31) == 0) red[tid >> 5] = dsum;
    __syncthreads();
    if (tid == 0) {
        float tot = 0.0f;
        #pragma unroll
        for (int k = 0; k < 8; ++k) tot += red[k];
        atomicAdd(&g_diff, tot);
    }
}

// ---------------------------------------------------------------- loss ----
__global__ void final_kernel(float* __restrict__ loss_out) {
    __shared__ float w[8];
    int t = threadIdx.x;
    float v = g_sum[t];
    float s = v * v;
    #pragma unroll
    for (int o = 16; o > 0; o >>= 1) s += __shfl_xor_sync(0xffffffffu, s, o);
    if ((t & 31) == 0) w[t >> 5] = s;
    __syncthreads();
    if (t == 0) {
        float snorm2 = 0.0f;
        #pragma unroll
        for (int k = 0; k < 8; ++k) snorm2 += w[k];
        float entropy = 2.0f * (float)NEMBED * g_ssqsum - 2.0f * snorm2;
        float diff = g_diff * (1.0f / (float)OUT_ELEMS);
        loss_out[0] = diff - entropy * (1.0f / ((float)NEMBED * (float)NEMBED));
    }
}

// -------------------------------------------------------------- launch ----
extern "C" void kernel_launch(void* const* d_in, const int* in_sizes, int n_in,
                              void* d_out, int out_size) {
    const float* input     = (const float*)d_in[0];
    const float* embedding = (const float*)d_in[1];
    float* out  = (float*)d_out;
    float* loss = out + LOSS_OFF;
    float* ind  = out + IND_OFF;

    cudaFuncSetAttribute(main_kernel,
                         cudaFuncAttributeMaxDynamicSharedMemorySize, SMEM_BYTES);

    init_kernel<<<1, 256>>>();
    normalize_kernel<<<NEMBED, 256>>>(embedding);
    main_kernel<<<NROWS / BM, 256, SMEM_BYTES>>>(input, out, ind);
    final_kernel<<<1, 256>>>(loss);
}